// round 1
// baseline (speedup 1.0000x reference)
#include <cuda_runtime.h>

// Problem shapes (fixed by reference):
//   lx_in, ux_in : (32,32,32,32,32) fp32 -> 32768 rows x 1024 inner
//   lc_in, uc_in : (32,32,32)
//   x_min, x_max : (32,32) = 1024 elems
// Outputs concatenated in d_out: [lx_out | ux_out | lc_out | uc_out]

#define NROWS 32768
#define INNER 1024
#define NTHREADS 256   // 4 elems (one float4) per thread

__global__ __launch_bounds__(NTHREADS)
void crown_relu_kernel(const float* __restrict__ lx_in,
                       const float* __restrict__ ux_in,
                       const float* __restrict__ lc_in,
                       const float* __restrict__ uc_in,
                       const float* __restrict__ x_min,
                       const float* __restrict__ x_max,
                       float* __restrict__ lx_out,
                       float* __restrict__ ux_out,
                       float* __restrict__ lc_out,
                       float* __restrict__ uc_out)
{
    const int row = blockIdx.x;
    const int t   = threadIdx.x;
    const long long base4 = (long long)row * (INNER / 4);

    const float4* lx4 = reinterpret_cast<const float4*>(lx_in) + base4;
    const float4* ux4 = reinterpret_cast<const float4*>(ux_in) + base4;
    const float4* mn4 = reinterpret_cast<const float4*>(x_min);
    const float4* mx4 = reinterpret_cast<const float4*>(x_max);

    // Register-resident loads (read each input byte exactly once)
    float4 lv = lx4[t];
    float4 uv = ux4[t];
    float4 mn = mn4[t];
    float4 mx = mx4[t];

    // mask_lower * lx == min(lx*x_min, lx*x_max); mask_upper * ux == max(...)
    float sl = fminf(lv.x * mn.x, lv.x * mx.x)
             + fminf(lv.y * mn.y, lv.y * mx.y)
             + fminf(lv.z * mn.z, lv.z * mx.z)
             + fminf(lv.w * mn.w, lv.w * mx.w);
    float su = fmaxf(uv.x * mn.x, uv.x * mx.x)
             + fmaxf(uv.y * mn.y, uv.y * mx.y)
             + fmaxf(uv.z * mn.z, uv.z * mx.z)
             + fmaxf(uv.w * mn.w, uv.w * mx.w);

    // Warp reduction of both sums
    #pragma unroll
    for (int off = 16; off > 0; off >>= 1) {
        sl += __shfl_down_sync(0xffffffffu, sl, off);
        su += __shfl_down_sync(0xffffffffu, su, off);
    }

    __shared__ float s_l[NTHREADS / 32];
    __shared__ float s_u[NTHREADS / 32];
    __shared__ float s_fl;  // lx/lc multiplier: alive ? 1 : 0
    __shared__ float s_fu;  // ux multiplier:    alive ? 1 : (cross ? slope : 0)

    const int lane = t & 31;
    const int wid  = t >> 5;
    if (lane == 0) { s_l[wid] = sl; s_u[wid] = su; }
    __syncthreads();

    if (t == 0) {
        float l = lc_in[row];
        float u = uc_in[row];
        #pragma unroll
        for (int w = 0; w < NTHREADS / 32; w++) { l += s_l[w]; u += s_u[w]; }

        bool alive = (l >= 0.0f);
        bool cross = (l < 0.0f) && (u > 0.0f);
        float slope = cross ? fminf(fmaxf(u / (u - l), 0.0f), 1.0f) : 1.0f;

        float fl = alive ? 1.0f : 0.0f;
        float fu = alive ? 1.0f : (cross ? slope : 0.0f);
        s_fl = fl;
        s_fu = fu;

        lc_out[row] = fl * lc_in[row];
        uc_out[row] = alive ? uc_in[row]
                            : (cross ? (slope * uc_in[row] - slope * l) : 0.0f);
    }
    __syncthreads();

    const float fl = s_fl;
    const float fu = s_fu;

    float4 lo, uo;
    lo.x = fl * lv.x; lo.y = fl * lv.y; lo.z = fl * lv.z; lo.w = fl * lv.w;
    uo.x = fu * uv.x; uo.y = fu * uv.y; uo.z = fu * uv.z; uo.w = fu * uv.w;

    reinterpret_cast<float4*>(lx_out)[base4 + t] = lo;
    reinterpret_cast<float4*>(ux_out)[base4 + t] = uo;
}

extern "C" void kernel_launch(void* const* d_in, const int* in_sizes, int n_in,
                              void* d_out, int out_size)
{
    const float* lx_in = (const float*)d_in[0];
    const float* ux_in = (const float*)d_in[1];
    const float* lc_in = (const float*)d_in[2];
    const float* uc_in = (const float*)d_in[3];
    const float* x_min = (const float*)d_in[4];
    const float* x_max = (const float*)d_in[5];

    float* out = (float*)d_out;
    const long long big = (long long)NROWS * INNER;   // 33,554,432
    float* lx_out = out;
    float* ux_out = out + big;
    float* lc_out = out + 2 * big;
    float* uc_out = out + 2 * big + NROWS;

    crown_relu_kernel<<<NROWS, NTHREADS>>>(lx_in, ux_in, lc_in, uc_in,
                                           x_min, x_max,
                                           lx_out, ux_out, lc_out, uc_out);
}